// round 5
// baseline (speedup 1.0000x reference)
#include <cuda_runtime.h>
#include <cuda_fp16.h>
#include <cstdint>

#define M_DIM 4096
#define N_DIM 8192
#define K_DIM 2048

#define BM 128
#define BN 256
#define BK 32
#define NIT (K_DIM / BK)      // 64
#define NSTAGE 4
#define LDS 40                          // halves per smem row (80B, conflict-free for ldmatrix)
#define A_HALVES (BM * LDS)             // 5120
#define B_HALVES (BN * LDS)             // 10240
#define STAGE_HALVES (A_HALVES + B_HALVES)  // 15360 (30720 B)
#define SMEM_BYTES (NSTAGE * STAGE_HALVES * 2)  // 122880

// Static scratch (allocation-free rule): fp16 weights + fp16 activations
__device__ __align__(16) __half g_w[(size_t)N_DIM * K_DIM];  // 32 MB
__device__ __align__(16) __half g_x[(size_t)M_DIM * K_DIM];  // 16 MB

__constant__ float c_lut[16] = {
    -1.0f, -0.5f, -0.333333f, -0.2f, -0.142857f, -0.090909f, -0.076923f,
    0.0f, 0.076923f, 0.090909f, 0.142857f, 0.2f, 0.333333f, 0.5f, 1.0f, 0.0f};

// ---------------------------------------------------------------------------
// Dequant: smem LUT (16 words -> 16 distinct banks, broadcast on repeats)
// ---------------------------------------------------------------------------
__global__ __launch_bounds__(256) void dequant_kernel(const int* __restrict__ gi,
                                                      const float* __restrict__ scale_p) {
    __shared__ float lut[16];
    if (threadIdx.x < 16) lut[threadIdx.x] = c_lut[threadIdx.x] * (*scale_p);
    __syncthreads();
    size_t t = (size_t)blockIdx.x * blockDim.x + threadIdx.x;
    const int4* gp = reinterpret_cast<const int4*>(gi) + t * 2;
    int4 a = gp[0];
    int4 b = gp[1];
    __half2 h0 = __floats2half2_rn(lut[a.x], lut[a.y]);
    __half2 h1 = __floats2half2_rn(lut[a.z], lut[a.w]);
    __half2 h2 = __floats2half2_rn(lut[b.x], lut[b.y]);
    __half2 h3 = __floats2half2_rn(lut[b.z], lut[b.w]);
    uint4 o;
    o.x = *reinterpret_cast<uint32_t*>(&h0);
    o.y = *reinterpret_cast<uint32_t*>(&h1);
    o.z = *reinterpret_cast<uint32_t*>(&h2);
    o.w = *reinterpret_cast<uint32_t*>(&h3);
    *reinterpret_cast<uint4*>(g_w + t * 8) = o;
}

// ---------------------------------------------------------------------------
// Convert activations fp32 -> fp16, 8 per thread
// ---------------------------------------------------------------------------
__global__ __launch_bounds__(256) void xconv_kernel(const float* __restrict__ x) {
    size_t t = (size_t)blockIdx.x * blockDim.x + threadIdx.x;
    const float4* xp = reinterpret_cast<const float4*>(x) + t * 2;
    float4 a = xp[0];
    float4 b = xp[1];
    __half2 h0 = __floats2half2_rn(a.x, a.y);
    __half2 h1 = __floats2half2_rn(a.z, a.w);
    __half2 h2 = __floats2half2_rn(b.x, b.y);
    __half2 h3 = __floats2half2_rn(b.z, b.w);
    uint4 o;
    o.x = *reinterpret_cast<uint32_t*>(&h0);
    o.y = *reinterpret_cast<uint32_t*>(&h1);
    o.z = *reinterpret_cast<uint32_t*>(&h2);
    o.w = *reinterpret_cast<uint32_t*>(&h3);
    *reinterpret_cast<uint4*>(g_x + t * 8) = o;
}

// ---------------------------------------------------------------------------
// helpers
// ---------------------------------------------------------------------------
__device__ __forceinline__ void cp16(__half* dst, const __half* src) {
    uint32_t d = (uint32_t)__cvta_generic_to_shared(dst);
    asm volatile("cp.async.cg.shared.global [%0], [%1], 16;\n" :: "r"(d), "l"(src));
}

__device__ __forceinline__ void ldsm4(uint32_t* r, const __half* p) {
    uint32_t a = (uint32_t)__cvta_generic_to_shared(p);
    asm volatile("ldmatrix.sync.aligned.m8n8.x4.shared.b16 {%0,%1,%2,%3}, [%4];\n"
                 : "=r"(r[0]), "=r"(r[1]), "=r"(r[2]), "=r"(r[3]) : "r"(a));
}

__device__ __forceinline__ void mma16816(float* c, const uint32_t* a, const uint32_t* b) {
    asm volatile(
        "mma.sync.aligned.m16n8k16.row.col.f32.f16.f16.f32 "
        "{%0,%1,%2,%3}, {%4,%5,%6,%7}, {%8,%9}, {%0,%1,%2,%3};\n"
        : "+f"(c[0]), "+f"(c[1]), "+f"(c[2]), "+f"(c[3])
        : "r"(a[0]), "r"(a[1]), "r"(a[2]), "r"(a[3]), "r"(b[0]), "r"(b[1]));
}

// ---------------------------------------------------------------------------
// GEMM: out[M,N] = g_x[M,K] @ g_w[N,K]^T
// CTA tile 128x256x32, 256 threads, 8 warps arranged 2(M) x 4(N),
// warp tile 64x64. 4-stage cp.async pipeline, one __syncthreads per iter.
// ---------------------------------------------------------------------------
__global__ __launch_bounds__(256, 1) void gemm_kernel(float* __restrict__ out) {
    extern __shared__ __half sm[];

    const int tid = threadIdx.x;
    const int warp = tid >> 5;
    const int lane = tid & 31;
    const int wm = warp >> 2;     // 0..1 : 64-row slice
    const int wn = warp & 3;      // 0..3 : 64-col slice
    const int m0 = blockIdx.y * BM;
    const int n0 = blockIdx.x * BN;

    const int lr = tid >> 2;            // 0..63
    const int lc = (tid & 3) * 8;       // 0,8,16,24 halves

    float acc[4][8][4];
#pragma unroll
    for (int i = 0; i < 4; i++)
#pragma unroll
        for (int j = 0; j < 8; j++)
#pragma unroll
            for (int k = 0; k < 4; k++) acc[i][j][k] = 0.0f;

    auto load_stage = [&](int s, int k0) {
        __half* a = sm + s * STAGE_HALVES;
        __half* b = a + A_HALVES;
        const __half* ga = g_x + (size_t)(m0 + lr) * K_DIM + k0 + lc;
        cp16(a + lr * LDS + lc,        ga);
        cp16(a + (lr + 64) * LDS + lc, ga + (size_t)64 * K_DIM);
        const __half* gb = g_w + (size_t)(n0 + lr) * K_DIM + k0 + lc;
#pragma unroll
        for (int c = 0; c < 4; c++)
            cp16(b + (lr + c * 64) * LDS + lc, gb + (size_t)(c * 64) * K_DIM);
        asm volatile("cp.async.commit_group;\n");
    };

    // prologue: 3 stages in flight
    load_stage(0, 0);
    load_stage(1, BK);
    load_stage(2, 2 * BK);

    for (int it = 0; it < NIT; ++it) {
        asm volatile("cp.async.wait_group 2;\n");
        __syncthreads();   // stage `it` visible to all; all warps done with stage it-1

        if (it + 3 < NIT) load_stage((it + 3) & 3, (it + 3) * BK);  // reuses slot (it-1)&3

        const __half* a_s = sm + (it & 3) * STAGE_HALVES;
        const __half* b_s = a_s + A_HALVES;

#pragma unroll
        for (int kk = 0; kk < BK; kk += 16) {
            uint32_t af[4][4];
#pragma unroll
            for (int mt = 0; mt < 4; mt++) {
                const __half* p = a_s + (wm * 64 + mt * 16 + (lane & 15)) * LDS
                                      + kk + (lane >> 4) * 8;
                ldsm4(af[mt], p);
            }
            uint32_t bf[8][2];
#pragma unroll
            for (int np = 0; np < 4; np++) {
                const __half* p = b_s + (wn * 64 + np * 16 + (lane & 7) + ((lane >> 4) & 1) * 8) * LDS
                                      + kk + ((lane >> 3) & 1) * 8;
                uint32_t r[4];
                ldsm4(r, p);
                bf[np * 2][0] = r[0]; bf[np * 2][1] = r[1];
                bf[np * 2 + 1][0] = r[2]; bf[np * 2 + 1][1] = r[3];
            }
#pragma unroll
            for (int mt = 0; mt < 4; mt++)
#pragma unroll
                for (int nt = 0; nt < 8; nt++)
                    mma16816(acc[mt][nt], af[mt], bf[nt]);
        }
    }

    // epilogue: direct fp32 stores
#pragma unroll
    for (int mt = 0; mt < 4; mt++) {
#pragma unroll
        for (int nt = 0; nt < 8; nt++) {
            int row = m0 + wm * 64 + mt * 16 + (lane >> 2);
            int col = n0 + wn * 64 + nt * 8 + (lane & 3) * 2;
            float2 v0 = make_float2(acc[mt][nt][0], acc[mt][nt][1]);
            float2 v1 = make_float2(acc[mt][nt][2], acc[mt][nt][3]);
            *reinterpret_cast<float2*>(out + (size_t)row * N_DIM + col) = v0;
            *reinterpret_cast<float2*>(out + (size_t)(row + 8) * N_DIM + col) = v1;
        }
    }
}

// ---------------------------------------------------------------------------
// kernel_launch
// ---------------------------------------------------------------------------
extern "C" void kernel_launch(void* const* d_in, const int* in_sizes, int n_in,
                              void* d_out, int out_size) {
    const float* x = (const float*)d_in[0];
    const int* gi = (const int*)d_in[1];
    const float* scale = (const float*)d_in[2];
    float* out = (float*)d_out;

    dequant_kernel<<<(N_DIM * (K_DIM / 8)) / 256, 256>>>(gi, scale);   // 8192 blocks
    xconv_kernel<<<(M_DIM * (K_DIM / 8)) / 256, 256>>>(x);             // 4096 blocks

    cudaFuncSetAttribute(gemm_kernel, cudaFuncAttributeMaxDynamicSharedMemorySize, SMEM_BYTES);
    dim3 grid(N_DIM / BN, M_DIM / BM);  // (32, 32)
    gemm_kernel<<<grid, 256, SMEM_BYTES>>>(out);
}